// round 4
// baseline (speedup 1.0000x reference)
#include <cuda_runtime.h>
#include <math.h>

#define L 256
#define B 32
#define C 64
#define LB (L * B)           // 8192
#define LBC (LB * C)         // 524288
#define DMAX 12              // exp(-13^2/8)=6.7e-10: below tolerance for this problem
#define TL 32                // rows per msg block
#define RPT 8                // rows per thread in msg kernel
#define NBUCKET 256

// Scratch (allocation-free rule: __device__ globals)
__device__ float g_fmp[LBC];
__device__ float g_fmf[LBC];
__device__ float g_smp[LBC];
__device__ float g_smf[LBC];
__device__ float g_buckets[NBUCKET];

// Gaussian weights exp(-d*d/8) as COMPILE-TIME literals -> FFMA-imm (rt=1/SMSP)
__device__ __forceinline__ constexpr float wexp(int d) {
    constexpr float w[13] = {
        1.0f,
        0.882496903f,   0.606530660f,   0.324652467f,   0.135335283f,
        0.0439369336f,  0.0111089965f,  0.00218749111f, 0.000335462624f,
        4.00652974e-05f, 3.72665317e-06f, 2.69957964e-07f, 1.52299797e-08f};
    return w[d];
}

// ---------------------------------------------------------------------------
// Kernel 1: Gaussian-decay message passing as a +/-DMAX stencil.
// grid: (L/TL, B, 2)  z: 0 -> f, 1 -> s. 256 threads.
// ---------------------------------------------------------------------------
__global__ void __launch_bounds__(256) msg_kernel(const float* __restrict__ f,
                                                  const float* __restrict__ s) {
    __shared__ float tile[(TL + 2 * DMAX) * C];   // 56*64*4 = 14.3 KB

    const int tid = threadIdx.x;
    const int l0  = blockIdx.x * TL;
    const int b   = blockIdx.y;
    const int tz  = blockIdx.z;

    if (blockIdx.x == 0 && blockIdx.y == 0 && blockIdx.z == 0 && tid < NBUCKET)
        g_buckets[tid] = 0.0f;

    const float* __restrict__ x  = (tz == 0) ? f : s;
    float* __restrict__ mp = (tz == 0) ? g_fmp : g_smp;
    float* __restrict__ mf = (tz == 0) ? g_fmf : g_smf;

#pragma unroll
    for (int i = tid; i < (TL + 2 * DMAX) * C; i += 256) {
        int row = i >> 6;
        int c   = i & 63;
        int lg  = l0 - DMAX + row;
        tile[i] = (lg >= 0 && lg < L) ? x[((size_t)lg * B + b) * C + c] : 0.0f;
    }
    __syncthreads();

    const int c  = tid & 63;
    const int j0 = (tid >> 6) * RPT;     // local output row base (0,8,16,24)

    float ap[RPT], af[RPT];
#pragma unroll
    for (int r = 0; r < RPT; ++r) { ap[r] = 0.0f; af[r] = 0.0f; }

#pragma unroll
    for (int k = 0; k < RPT + 2 * DMAX; ++k) {
        const float xi = tile[(j0 + k) * C + c];
#pragma unroll
        for (int r = 0; r < RPT; ++r) {
            const int d = k - DMAX - r;       // compile-time per (k,r)
            if (d >= -DMAX && d <= -1) ap[r] = fmaf(wexp(-d), xi, ap[r]);
            else if (d >= 1 && d <= DMAX) af[r] = fmaf(wexp(d), xi, af[r]);
        }
    }

#pragma unroll
    for (int r = 0; r < RPT; ++r) {
        const int l = l0 + j0 + r;
        const size_t o = ((size_t)l * B + b) * C + c;
        mp[o] = ap[r] / (float)max(l, 1);
        mf[o] = af[r] / (float)max(L - 1 - l, 1);
    }
}

// warp-level softmax + CE over 64 logits (lane holds j=lane and j=lane+32).
__device__ __forceinline__ float warp_softmax_ce(float v0, float v1, int lane,
                                                 int label, float* outp) {
    float m = fmaxf(v0, v1);
#pragma unroll
    for (int o = 16; o; o >>= 1) m = fmaxf(m, __shfl_xor_sync(0xffffffffu, m, o));
    float e0 = __expf(v0 - m), e1 = __expf(v1 - m);
    float sum = e0 + e1;
#pragma unroll
    for (int o = 16; o; o >>= 1) sum += __shfl_xor_sync(0xffffffffu, sum, o);
    if (outp) {
        const float inv = 1.0f / sum;
        outp[lane]      = e0 * inv;
        outp[lane + 32] = e1 * inv;
    }
    const float lse = m + __logf(sum);
    const float vl  = __shfl_sync(0xffffffffu, (label < 32) ? v0 : v1, label & 31);
    return lse - vl;
}

// ---------------------------------------------------------------------------
// Kernel 2: one CTA per (l,b). Streams the 5 matrices (80 KB) once.
// Register accumulation across the 5 sequential matrix passes; single
// reduction at the end. (R2-proven structure; only occupancy changed.)
// ---------------------------------------------------------------------------

// M @ vcol -> row partials RACC; M^T @ vrow -> col partials CACC
#define PROC(M, VC, VR, RACC, CACC)                                          \
    {                                                                          \
        const float4 vc = *(const float4*)((VC) + (li << 2));                  \
        _Pragma("unroll")                                                      \
        for (int rp = 0; rp < 4; ++rp) {                                       \
            const int r = rbase + (rp << 1);                                   \
            const float4 m = *(const float4*)((M) + (r << 6) + (li << 2));     \
            RACC[rp] = fmaf(m.x, vc.x,                                         \
                       fmaf(m.y, vc.y,                                         \
                       fmaf(m.z, vc.z,                                         \
                       fmaf(m.w, vc.w, RACC[rp]))));                           \
            const float vr = (VR)[r];                                          \
            CACC.x = fmaf(m.x, vr, CACC.x);                                    \
            CACC.y = fmaf(m.y, vr, CACC.y);                                    \
            CACC.z = fmaf(m.z, vr, CACC.z);                                    \
            CACC.w = fmaf(m.w, vr, CACC.w);                                    \
        }                                                                      \
    }

__global__ void __launch_bounds__(256, 5)
main_kernel(const float* __restrict__ f,  const float* __restrict__ s,
            const float* __restrict__ fs, const float* __restrict__ ff,
            const float* __restrict__ ss, const float* __restrict__ fs_t,
            const float* __restrict__ sf_t,
            const int* __restrict__ f_lab, const int* __restrict__ s_lab,
            float* __restrict__ out) {
    const int blk = blockIdx.x;                 // l*B + b
    const size_t voff = (size_t)blk * C;
    const size_t moff = (size_t)blk * (C * C);
    const int tid = threadIdx.x;

    __shared__ __align__(16) float sf0[C], ss0[C];
    __shared__ __align__(16) float v_fmp[C], v_fmf[C], v_smp[C], v_smf[C];
    __shared__ __align__(16) float v_fW[C], v_sW[C];
    __shared__ __align__(16) float accF[C], accS[C];
    __shared__ float lossAcc;

    if (tid < C) {
        const float fv = f[voff + tid];
        const float sv = s[voff + tid];
        sf0[tid] = fv;          ss0[tid] = sv;
        v_fW[tid] = 0.5f * fv;  v_sW[tid] = 0.5f * sv;            // W_S
        v_fmp[tid] = 0.5f * g_fmp[voff + tid];                     // W_T folded
        v_fmf[tid] = 0.5f * g_fmf[voff + tid];
        v_smp[tid] = 0.5f * g_smp[voff + tid];
        v_smf[tid] = 0.5f * g_smf[voff + tid];
    }
    if (tid == 0) lossAcc = 0.0f;
    __syncthreads();

    const int w    = tid >> 5;
    const int lane = tid & 31;
    const int half = lane >> 4;   // 0 or 1
    const int li   = lane & 15;   // column group
    const int rbase = (w << 3) + half;

    float rowF[4] = {0.f, 0.f, 0.f, 0.f};
    float rowS[4] = {0.f, 0.f, 0.f, 0.f};
    float4 colF = make_float4(0.f, 0.f, 0.f, 0.f);
    float4 colS = make_float4(0.f, 0.f, 0.f, 0.f);

    // next_f row: ff@(wT f_mf), fs@(wS s), fs_t@(wT s_mf)
    // next_f col: ff^T@(wT f_mp), sf_t^T@(wT s_mp)
    // next_s row: ss@(wT s_mf), sf_t@(wT f_mf)
    // next_s col: ss^T@(wT s_mp), fs^T@(wS f), fs_t^T@(wT f_mp)
    PROC(ff   + moff, v_fmf, v_fmp, rowF, colF);
    PROC(ss   + moff, v_smf, v_smp, rowS, colS);
    PROC(fs   + moff, v_sW,  v_fW,  rowF, colS);
    PROC(fs_t + moff, v_smf, v_fmp, rowF, colS);
    PROC(sf_t + moff, v_fmf, v_smp, rowS, colF);

    // ---- row reduction: sum over 16 li-lanes within each half ----
#pragma unroll
    for (int rp = 0; rp < 4; ++rp) {
#pragma unroll
        for (int o = 8; o; o >>= 1) {
            rowF[rp] += __shfl_xor_sync(0xffffffffu, rowF[rp], o);
            rowS[rp] += __shfl_xor_sync(0xffffffffu, rowS[rp], o);
        }
    }
    if (li == 0) {
#pragma unroll
        for (int rp = 0; rp < 4; ++rp) {
            const int r = rbase + (rp << 1);
            accF[r] = rowF[rp];     // exclusive per row -> plain store
            accS[r] = rowS[rp];
        }
    }
    __syncthreads();

    // ---- col reduction: fold odd half into even, then atomics across warps
    colF.x += __shfl_down_sync(0xffffffffu, colF.x, 16);
    colF.y += __shfl_down_sync(0xffffffffu, colF.y, 16);
    colF.z += __shfl_down_sync(0xffffffffu, colF.z, 16);
    colF.w += __shfl_down_sync(0xffffffffu, colF.w, 16);
    colS.x += __shfl_down_sync(0xffffffffu, colS.x, 16);
    colS.y += __shfl_down_sync(0xffffffffu, colS.y, 16);
    colS.z += __shfl_down_sync(0xffffffffu, colS.z, 16);
    colS.w += __shfl_down_sync(0xffffffffu, colS.w, 16);
    if (half == 0) {
        const int cb = li << 2;
        atomicAdd(&accF[cb + 0], colF.x);
        atomicAdd(&accF[cb + 1], colF.y);
        atomicAdd(&accF[cb + 2], colF.z);
        atomicAdd(&accF[cb + 3], colF.w);
        atomicAdd(&accS[cb + 0], colS.x);
        atomicAdd(&accS[cb + 1], colS.y);
        atomicAdd(&accS[cb + 2], colS.z);
        atomicAdd(&accS[cb + 3], colS.w);
    }
    __syncthreads();

    // ---- epilogue: softmax + CE (old & new logits), outputs, loss partial
    if (w == 0) {
        const int lab = f_lab[blk];
        const float a0 = sf0[lane], a1 = sf0[lane + 32];
        const float ce0 = warp_softmax_ce(a0, a1, lane, lab, nullptr);
        const float n0 = a0 + accF[lane], n1 = a1 + accF[lane + 32];
        const float ce1 = warp_softmax_ce(n0, n1, lane, lab, out + voff);
        if (lane == 0) atomicAdd(&lossAcc, ce0 + ce1);
    } else if (w == 1) {
        const int lab = s_lab[blk];
        const float a0 = ss0[lane], a1 = ss0[lane + 32];
        const float ce0 = warp_softmax_ce(a0, a1, lane, lab, nullptr);
        const float n0 = a0 + accS[lane], n1 = a1 + accS[lane + 32];
        const float ce1 = warp_softmax_ce(n0, n1, lane, lab, out + (size_t)LBC + voff);
        if (lane == 0) atomicAdd(&lossAcc, ce0 + ce1);
    }
    __syncthreads();
    if (tid == 0) atomicAdd(&g_buckets[blk & (NBUCKET - 1)], lossAcc);
}

// ---------------------------------------------------------------------------
// Kernel 3: deterministic bucket reduction -> loss scalar.
// ---------------------------------------------------------------------------
__global__ void loss_finalize(float* __restrict__ out_loss) {
    __shared__ float sm[NBUCKET];
    const int t = threadIdx.x;
    sm[t] = g_buckets[t];
    __syncthreads();
    for (int sct = NBUCKET / 2; sct > 0; sct >>= 1) {
        if (t < sct) sm[t] += sm[t + sct];
        __syncthreads();
    }
    if (t == 0) out_loss[0] = sm[0] * (1.0f / (float)LB);
}

// ---------------------------------------------------------------------------
extern "C" void kernel_launch(void* const* d_in, const int* in_sizes, int n_in,
                              void* d_out, int out_size) {
    const float* f    = (const float*)d_in[0];
    const float* s    = (const float*)d_in[1];
    const float* fs   = (const float*)d_in[2];
    const float* ff   = (const float*)d_in[3];
    const float* ss   = (const float*)d_in[4];
    const float* fs_t = (const float*)d_in[5];
    const float* sf_t = (const float*)d_in[6];
    const int* f_lab  = (const int*)d_in[7];
    const int* s_lab  = (const int*)d_in[8];
    float* out = (float*)d_out;

    dim3 g1(L / TL, B, 2);
    msg_kernel<<<g1, 256>>>(f, s);
    main_kernel<<<LB, 256>>>(f, s, fs, ff, ss, fs_t, sf_t, f_lab, s_lab, out);
    loss_finalize<<<1, NBUCKET>>>(out + (size_t)2 * LBC);
}

// round 5
// speedup vs baseline: 1.0312x; 1.0312x over previous
#include <cuda_runtime.h>
#include <math.h>

#define L 256
#define B 32
#define C 64
#define LB (L * B)           // 8192
#define LBC (LB * C)         // 524288
#define DMAX 12              // exp(-13^2/8)=6.7e-10: below tolerance here
#define WROWS (2 * DMAX + 1) // 25
#define NBUCKET 256

// Scratch (allocation-free rule: __device__ globals)
__device__ float g_buckets[NBUCKET];   // zero-initialized; finalize re-zeros

// Gaussian weights exp(-d*d/8) as COMPILE-TIME literals -> FFMA-imm
__device__ __forceinline__ constexpr float wexp(int d) {
    constexpr float w[13] = {
        1.0f,
        0.882496903f,   0.606530660f,   0.324652467f,   0.135335283f,
        0.0439369336f,  0.0111089965f,  0.00218749111f, 0.000335462624f,
        4.00652974e-05f, 3.72665317e-06f, 2.69957964e-07f, 1.52299797e-08f};
    return w[d];
}

// warp-level softmax + CE over 64 logits (lane holds j=lane and j=lane+32).
__device__ __forceinline__ float warp_softmax_ce(float v0, float v1, int lane,
                                                 int label, float* outp) {
    float m = fmaxf(v0, v1);
#pragma unroll
    for (int o = 16; o; o >>= 1) m = fmaxf(m, __shfl_xor_sync(0xffffffffu, m, o));
    float e0 = __expf(v0 - m), e1 = __expf(v1 - m);
    float sum = e0 + e1;
#pragma unroll
    for (int o = 16; o; o >>= 1) sum += __shfl_xor_sync(0xffffffffu, sum, o);
    if (outp) {
        const float inv = 1.0f / sum;
        outp[lane]      = e0 * inv;
        outp[lane + 32] = e1 * inv;
    }
    const float lse = m + __logf(sum);
    const float vl  = __shfl_sync(0xffffffffu, (label < 32) ? v0 : v1, label & 31);
    return lse - vl;
}

// M @ vcol -> row partials RACC; M^T @ vrow -> col partials CACC
// (R2-proven hot-loop structure: plain loads, sequential passes,
//  all reductions deferred to the end.)
#define PROC(M, VC, VR, RACC, CACC)                                          \
    {                                                                          \
        const float4 vc = *(const float4*)((VC) + (li << 2));                  \
        _Pragma("unroll")                                                      \
        for (int rp = 0; rp < 4; ++rp) {                                       \
            const int r = rbase + (rp << 1);                                   \
            const float4 m = *(const float4*)((M) + (r << 6) + (li << 2));     \
            RACC[rp] = fmaf(m.x, vc.x,                                         \
                       fmaf(m.y, vc.y,                                         \
                       fmaf(m.z, vc.z,                                         \
                       fmaf(m.w, vc.w, RACC[rp]))));                           \
            const float vr = (VR)[r];                                          \
            CACC.x = fmaf(m.x, vr, CACC.x);                                    \
            CACC.y = fmaf(m.y, vr, CACC.y);                                    \
            CACC.z = fmaf(m.z, vr, CACC.z);                                    \
            CACC.w = fmaf(m.w, vr, CACC.w);                                    \
        }                                                                      \
    }

// ---------------------------------------------------------------------------
// Main kernel: one CTA per (l,b).
// Prologue: load +/-12-row window of f,s (L2-hot) and compute the four
// Gaussian message vectors in-block (replaces the old msg_kernel + 32MB
// scratch round-trip). Body: R2-proven streaming of the 5 matrices.
// ---------------------------------------------------------------------------
__global__ void __launch_bounds__(256, 4)
main_kernel(const float* __restrict__ f,  const float* __restrict__ s,
            const float* __restrict__ fs, const float* __restrict__ ff,
            const float* __restrict__ ss, const float* __restrict__ fs_t,
            const float* __restrict__ sf_t,
            const int* __restrict__ f_lab, const int* __restrict__ s_lab,
            float* __restrict__ out) {
    const int blk = blockIdx.x;                 // l*B + b
    const int l   = blk >> 5;                   // B = 32
    const int b   = blk & 31;
    const size_t voff = (size_t)blk * C;
    const size_t moff = (size_t)blk * (C * C);
    const int tid = threadIdx.x;

    __shared__ __align__(16) float winF[WROWS * C], winS[WROWS * C]; // 12.8KB
    __shared__ __align__(16) float sf0[C], ss0[C];
    __shared__ __align__(16) float v_fmp[C], v_fmf[C], v_smp[C], v_smf[C];
    __shared__ __align__(16) float v_fW[C], v_sW[C];
    __shared__ __align__(16) float accF[C], accS[C];
    __shared__ float lossAcc;

    // ---- prologue: window load (zero-padded) ----
#pragma unroll
    for (int i = tid; i < WROWS * C; i += 256) {
        const int row = i >> 6;
        const int c   = i & 63;
        const int lg  = l - DMAX + row;
        const bool ok = (lg >= 0) && (lg < L);
        const size_t o = ((size_t)lg * B + b) * C + c;
        winF[i] = ok ? f[o] : 0.0f;
        winS[i] = ok ? s[o] : 0.0f;
    }
    if (tid == 0) lossAcc = 0.0f;
    __syncthreads();

    // ---- prologue: in-block Gaussian stencil (12 FFMA-imm per thread) ----
    {
        const int c = tid & 63;
        const int q = tid >> 6;            // 0: f_mp, 1: f_mf, 2: s_mp, 3: s_mf
        const float* win = (q < 2) ? winF : winS;
        float acc = 0.0f;
        if ((q & 1) == 0) {                // past: rows l-d
#pragma unroll
            for (int d = 1; d <= DMAX; ++d)
                acc = fmaf(wexp(d), win[(DMAX - d) * C + c], acc);
            acc *= 0.5f / (float)max(l, 1);                      // W_T folded
        } else {                           // future: rows l+d
#pragma unroll
            for (int d = 1; d <= DMAX; ++d)
                acc = fmaf(wexp(d), win[(DMAX + d) * C + c], acc);
            acc *= 0.5f / (float)max(L - 1 - l, 1);
        }
        float* dst = (q == 0) ? v_fmp : (q == 1) ? v_fmf : (q == 2) ? v_smp : v_smf;
        dst[c] = acc;

        if (q == 0) {                      // center row = f[l,b,:], s[l,b,:]
            const float fv = winF[DMAX * C + c];
            const float sv = winS[DMAX * C + c];
            sf0[c] = fv;          ss0[c] = sv;
            v_fW[c] = 0.5f * fv;  v_sW[c] = 0.5f * sv;           // W_S folded
        }
    }
    __syncthreads();

    // ---- body: stream the 5 matrices (R2 structure, unchanged) ----
    const int w    = tid >> 5;
    const int lane = tid & 31;
    const int half = lane >> 4;   // 0 or 1
    const int li   = lane & 15;   // column group
    const int rbase = (w << 3) + half;

    float rowF[4] = {0.f, 0.f, 0.f, 0.f};
    float rowS[4] = {0.f, 0.f, 0.f, 0.f};
    float4 colF = make_float4(0.f, 0.f, 0.f, 0.f);
    float4 colS = make_float4(0.f, 0.f, 0.f, 0.f);

    // next_f row: ff@(wT f_mf), fs@(wS s), fs_t@(wT s_mf)
    // next_f col: ff^T@(wT f_mp), sf_t^T@(wT s_mp)
    // next_s row: ss@(wT s_mf), sf_t@(wT f_mf)
    // next_s col: ss^T@(wT s_mp), fs^T@(wS f), fs_t^T@(wT f_mp)
    PROC(ff   + moff, v_fmf, v_fmp, rowF, colF);
    PROC(ss   + moff, v_smf, v_smp, rowS, colS);
    PROC(fs   + moff, v_sW,  v_fW,  rowF, colS);
    PROC(fs_t + moff, v_smf, v_fmp, rowF, colS);
    PROC(sf_t + moff, v_fmf, v_smp, rowS, colF);

    // ---- row reduction: sum over 16 li-lanes within each half ----
#pragma unroll
    for (int rp = 0; rp < 4; ++rp) {
#pragma unroll
        for (int o = 8; o; o >>= 1) {
            rowF[rp] += __shfl_xor_sync(0xffffffffu, rowF[rp], o);
            rowS[rp] += __shfl_xor_sync(0xffffffffu, rowS[rp], o);
        }
    }
    if (li == 0) {
#pragma unroll
        for (int rp = 0; rp < 4; ++rp) {
            const int r = rbase + (rp << 1);
            accF[r] = rowF[rp];     // exclusive per row -> plain store
            accS[r] = rowS[rp];
        }
    }
    __syncthreads();

    // ---- col reduction: fold odd half into even, then atomics across warps
    colF.x += __shfl_down_sync(0xffffffffu, colF.x, 16);
    colF.y += __shfl_down_sync(0xffffffffu, colF.y, 16);
    colF.z += __shfl_down_sync(0xffffffffu, colF.z, 16);
    colF.w += __shfl_down_sync(0xffffffffu, colF.w, 16);
    colS.x += __shfl_down_sync(0xffffffffu, colS.x, 16);
    colS.y += __shfl_down_sync(0xffffffffu, colS.y, 16);
    colS.z += __shfl_down_sync(0xffffffffu, colS.z, 16);
    colS.w += __shfl_down_sync(0xffffffffu, colS.w, 16);
    if (half == 0) {
        const int cb = li << 2;
        atomicAdd(&accF[cb + 0], colF.x);
        atomicAdd(&accF[cb + 1], colF.y);
        atomicAdd(&accF[cb + 2], colF.z);
        atomicAdd(&accF[cb + 3], colF.w);
        atomicAdd(&accS[cb + 0], colS.x);
        atomicAdd(&accS[cb + 1], colS.y);
        atomicAdd(&accS[cb + 2], colS.z);
        atomicAdd(&accS[cb + 3], colS.w);
    }
    __syncthreads();

    // ---- epilogue: softmax + CE (old & new logits), outputs, loss partial
    if (w == 0) {
        const int lab = f_lab[blk];
        const float a0 = sf0[lane], a1 = sf0[lane + 32];
        const float ce0 = warp_softmax_ce(a0, a1, lane, lab, nullptr);
        const float n0 = a0 + accF[lane], n1 = a1 + accF[lane + 32];
        const float ce1 = warp_softmax_ce(n0, n1, lane, lab, out + voff);
        if (lane == 0) atomicAdd(&lossAcc, ce0 + ce1);
    } else if (w == 1) {
        const int lab = s_lab[blk];
        const float a0 = ss0[lane], a1 = ss0[lane + 32];
        const float ce0 = warp_softmax_ce(a0, a1, lane, lab, nullptr);
        const float n0 = a0 + accS[lane], n1 = a1 + accS[lane + 32];
        const float ce1 = warp_softmax_ce(n0, n1, lane, lab, out + (size_t)LBC + voff);
        if (lane == 0) atomicAdd(&lossAcc, ce0 + ce1);
    }
    __syncthreads();
    if (tid == 0) atomicAdd(&g_buckets[blk & (NBUCKET - 1)], lossAcc);
}

// ---------------------------------------------------------------------------
// Finalize: deterministic bucket reduction -> loss scalar; re-zeros buckets
// so the next graph replay starts clean.
// ---------------------------------------------------------------------------
__global__ void loss_finalize(float* __restrict__ out_loss) {
    __shared__ float sm[NBUCKET];
    const int t = threadIdx.x;
    sm[t] = g_buckets[t];
    g_buckets[t] = 0.0f;                  // reset for next launch/replay
    __syncthreads();
    for (int sct = NBUCKET / 2; sct > 0; sct >>= 1) {
        if (t < sct) sm[t] += sm[t + sct];
        __syncthreads();
    }
    if (t == 0) out_loss[0] = sm[0] * (1.0f / (float)LB);
}

// ---------------------------------------------------------------------------
extern "C" void kernel_launch(void* const* d_in, const int* in_sizes, int n_in,
                              void* d_out, int out_size) {
    const float* f    = (const float*)d_in[0];
    const float* s    = (const float*)d_in[1];
    const float* fs   = (const float*)d_in[2];
    const float* ff   = (const float*)d_in[3];
    const float* ss   = (const float*)d_in[4];
    const float* fs_t = (const float*)d_in[5];
    const float* sf_t = (const float*)d_in[6];
    const int* f_lab  = (const int*)d_in[7];
    const int* s_lab  = (const int*)d_in[8];
    float* out = (float*)d_out;

    main_kernel<<<LB, 256>>>(f, s, fs, ff, ss, fs_t, sf_t, f_lab, s_lab, out);
    loss_finalize<<<1, NBUCKET>>>(out + (size_t)2 * LBC);
}

// round 6
// speedup vs baseline: 1.1123x; 1.0786x over previous
#include <cuda_runtime.h>
#include <math.h>

#define L 256
#define B 32
#define C 64
#define LB (L * B)           // 8192
#define LBC (LB * C)         // 524288
#define DMAX 12              // exp(-13^2/8)=6.7e-10: below tolerance here
#define TL 32                // rows per msg block
#define RPT 8                // rows per thread in msg kernel
#define NBUCKET 256

// Scratch (allocation-free rule: __device__ globals)
__device__ float g_fmp[LBC];
__device__ float g_fmf[LBC];
__device__ float g_smp[LBC];
__device__ float g_smf[LBC];
__device__ float g_buckets[NBUCKET];

// Gaussian weights exp(-d*d/8) as COMPILE-TIME literals -> FFMA-imm (rt=1/SMSP)
__device__ __forceinline__ constexpr float wexp(int d) {
    constexpr float w[13] = {
        1.0f,
        0.882496903f,   0.606530660f,   0.324652467f,   0.135335283f,
        0.0439369336f,  0.0111089965f,  0.00218749111f, 0.000335462624f,
        4.00652974e-05f, 3.72665317e-06f, 2.69957964e-07f, 1.52299797e-08f};
    return w[d];
}

// ---------------------------------------------------------------------------
// Kernel 1: Gaussian-decay message passing as a +/-DMAX stencil.
// (R4-proven: 7.55us) grid: (L/TL, B, 2)  z: 0 -> f, 1 -> s. 256 threads.
// ---------------------------------------------------------------------------
__global__ void __launch_bounds__(256) msg_kernel(const float* __restrict__ f,
                                                  const float* __restrict__ s) {
    __shared__ float tile[(TL + 2 * DMAX) * C];   // 56*64*4 = 14.3 KB

    const int tid = threadIdx.x;
    const int l0  = blockIdx.x * TL;
    const int b   = blockIdx.y;
    const int tz  = blockIdx.z;

    if (blockIdx.x == 0 && blockIdx.y == 0 && blockIdx.z == 0 && tid < NBUCKET)
        g_buckets[tid] = 0.0f;

    const float* __restrict__ x  = (tz == 0) ? f : s;
    float* __restrict__ mp = (tz == 0) ? g_fmp : g_smp;
    float* __restrict__ mf = (tz == 0) ? g_fmf : g_smf;

#pragma unroll
    for (int i = tid; i < (TL + 2 * DMAX) * C; i += 256) {
        int row = i >> 6;
        int c   = i & 63;
        int lg  = l0 - DMAX + row;
        tile[i] = (lg >= 0 && lg < L) ? x[((size_t)lg * B + b) * C + c] : 0.0f;
    }
    __syncthreads();

    const int c  = tid & 63;
    const int j0 = (tid >> 6) * RPT;     // local output row base (0,8,16,24)

    float ap[RPT], af[RPT];
#pragma unroll
    for (int r = 0; r < RPT; ++r) { ap[r] = 0.0f; af[r] = 0.0f; }

#pragma unroll
    for (int k = 0; k < RPT + 2 * DMAX; ++k) {
        const float xi = tile[(j0 + k) * C + c];
#pragma unroll
        for (int r = 0; r < RPT; ++r) {
            const int d = k - DMAX - r;       // compile-time per (k,r)
            if (d >= -DMAX && d <= -1) ap[r] = fmaf(wexp(-d), xi, ap[r]);
            else if (d >= 1 && d <= DMAX) af[r] = fmaf(wexp(d), xi, af[r]);
        }
    }

#pragma unroll
    for (int r = 0; r < RPT; ++r) {
        const int l = l0 + j0 + r;
        const size_t o = ((size_t)l * B + b) * C + c;
        mp[o] = ap[r] / (float)max(l, 1);
        mf[o] = af[r] / (float)max(L - 1 - l, 1);
    }
}

// warp-level softmax + CE over 64 logits (lane holds j=lane and j=lane+32).
__device__ __forceinline__ float warp_softmax_ce(float v0, float v1, int lane,
                                                 int label, float* outp) {
    float m = fmaxf(v0, v1);
#pragma unroll
    for (int o = 16; o; o >>= 1) m = fmaxf(m, __shfl_xor_sync(0xffffffffu, m, o));
    float e0 = __expf(v0 - m), e1 = __expf(v1 - m);
    float sum = e0 + e1;
#pragma unroll
    for (int o = 16; o; o >>= 1) sum += __shfl_xor_sync(0xffffffffu, sum, o);
    if (outp) {
        const float inv = 1.0f / sum;
        outp[lane]      = e0 * inv;
        outp[lane + 32] = e1 * inv;
    }
    const float lse = m + __logf(sum);
    const float vl  = __shfl_sync(0xffffffffu, (label < 32) ? v0 : v1, label & 31);
    return lse - vl;
}

// ---------------------------------------------------------------------------
// Kernel 2: one CTA per (l,b). EXACT R2 body (best measured: ~111us).
// ---------------------------------------------------------------------------

// M @ vcol -> row partials RACC; M^T @ vrow -> col partials CACC
#define PROC(M, VC, VR, RACC, CACC)                                          \
    {                                                                          \
        const float4 vc = *(const float4*)((VC) + (li << 2));                  \
        _Pragma("unroll")                                                      \
        for (int rp = 0; rp < 4; ++rp) {                                       \
            const int r = rbase + (rp << 1);                                   \
            const float4 m = *(const float4*)((M) + (r << 6) + (li << 2));     \
            RACC[rp] = fmaf(m.x, vc.x,                                         \
                       fmaf(m.y, vc.y,                                         \
                       fmaf(m.z, vc.z,                                         \
                       fmaf(m.w, vc.w, RACC[rp]))));                           \
            const float vr = (VR)[r];                                          \
            CACC.x = fmaf(m.x, vr, CACC.x);                                    \
            CACC.y = fmaf(m.y, vr, CACC.y);                                    \
            CACC.z = fmaf(m.z, vr, CACC.z);                                    \
            CACC.w = fmaf(m.w, vr, CACC.w);                                    \
        }                                                                      \
    }

__global__ void __launch_bounds__(256, 4)
main_kernel(const float* __restrict__ f,  const float* __restrict__ s,
            const float* __restrict__ fs, const float* __restrict__ ff,
            const float* __restrict__ ss, const float* __restrict__ fs_t,
            const float* __restrict__ sf_t,
            const int* __restrict__ f_lab, const int* __restrict__ s_lab,
            float* __restrict__ out) {
    const int blk = blockIdx.x;                 // l*B + b
    const size_t voff = (size_t)blk * C;
    const size_t moff = (size_t)blk * (C * C);
    const int tid = threadIdx.x;

    __shared__ __align__(16) float sf0[C], ss0[C];
    __shared__ __align__(16) float v_fmp[C], v_fmf[C], v_smp[C], v_smf[C];
    __shared__ __align__(16) float v_fW[C], v_sW[C];
    __shared__ __align__(16) float accF[C], accS[C];
    __shared__ float lossAcc;

    if (tid < C) {
        const float fv = f[voff + tid];
        const float sv = s[voff + tid];
        sf0[tid] = fv;          ss0[tid] = sv;
        v_fW[tid] = 0.5f * fv;  v_sW[tid] = 0.5f * sv;            // W_S
        v_fmp[tid] = 0.5f * g_fmp[voff + tid];                     // W_T folded
        v_fmf[tid] = 0.5f * g_fmf[voff + tid];
        v_smp[tid] = 0.5f * g_smp[voff + tid];
        v_smf[tid] = 0.5f * g_smf[voff + tid];
    }
    if (tid == 0) lossAcc = 0.0f;
    __syncthreads();

    const int w    = tid >> 5;
    const int lane = tid & 31;
    const int half = lane >> 4;   // 0 or 1
    const int li   = lane & 15;   // column group
    const int rbase = (w << 3) + half;

    float rowF[4] = {0.f, 0.f, 0.f, 0.f};
    float rowS[4] = {0.f, 0.f, 0.f, 0.f};
    float4 colF = make_float4(0.f, 0.f, 0.f, 0.f);
    float4 colS = make_float4(0.f, 0.f, 0.f, 0.f);

    // next_f row: ff@(wT f_mf), fs@(wS s), fs_t@(wT s_mf)
    // next_f col: ff^T@(wT f_mp), sf_t^T@(wT s_mp)
    // next_s row: ss@(wT s_mf), sf_t@(wT f_mf)
    // next_s col: ss^T@(wT s_mp), fs^T@(wS f), fs_t^T@(wT f_mp)
    PROC(ff   + moff, v_fmf, v_fmp, rowF, colF);
    PROC(ss   + moff, v_smf, v_smp, rowS, colS);
    PROC(fs   + moff, v_sW,  v_fW,  rowF, colS);
    PROC(fs_t + moff, v_smf, v_fmp, rowF, colS);
    PROC(sf_t + moff, v_fmf, v_smp, rowS, colF);

    // ---- row reduction: sum over 16 li-lanes within each half ----
#pragma unroll
    for (int rp = 0; rp < 4; ++rp) {
#pragma unroll
        for (int o = 8; o; o >>= 1) {
            rowF[rp] += __shfl_xor_sync(0xffffffffu, rowF[rp], o);
            rowS[rp] += __shfl_xor_sync(0xffffffffu, rowS[rp], o);
        }
    }
    if (li == 0) {
#pragma unroll
        for (int rp = 0; rp < 4; ++rp) {
            const int r = rbase + (rp << 1);
            accF[r] = rowF[rp];     // exclusive per row -> plain store
            accS[r] = rowS[rp];
        }
    }
    __syncthreads();

    // ---- col reduction: fold odd half into even, then atomics across warps
    colF.x += __shfl_down_sync(0xffffffffu, colF.x, 16);
    colF.y += __shfl_down_sync(0xffffffffu, colF.y, 16);
    colF.z += __shfl_down_sync(0xffffffffu, colF.z, 16);
    colF.w += __shfl_down_sync(0xffffffffu, colF.w, 16);
    colS.x += __shfl_down_sync(0xffffffffu, colS.x, 16);
    colS.y += __shfl_down_sync(0xffffffffu, colS.y, 16);
    colS.z += __shfl_down_sync(0xffffffffu, colS.z, 16);
    colS.w += __shfl_down_sync(0xffffffffu, colS.w, 16);
    if (half == 0) {
        const int cb = li << 2;
        atomicAdd(&accF[cb + 0], colF.x);
        atomicAdd(&accF[cb + 1], colF.y);
        atomicAdd(&accF[cb + 2], colF.z);
        atomicAdd(&accF[cb + 3], colF.w);
        atomicAdd(&accS[cb + 0], colS.x);
        atomicAdd(&accS[cb + 1], colS.y);
        atomicAdd(&accS[cb + 2], colS.z);
        atomicAdd(&accS[cb + 3], colS.w);
    }
    __syncthreads();

    // ---- epilogue: softmax + CE (old & new logits), outputs, loss partial
    if (w == 0) {
        const int lab = f_lab[blk];
        const float a0 = sf0[lane], a1 = sf0[lane + 32];
        const float ce0 = warp_softmax_ce(a0, a1, lane, lab, nullptr);
        const float n0 = a0 + accF[lane], n1 = a1 + accF[lane + 32];
        const float ce1 = warp_softmax_ce(n0, n1, lane, lab, out + voff);
        if (lane == 0) atomicAdd(&lossAcc, ce0 + ce1);
    } else if (w == 1) {
        const int lab = s_lab[blk];
        const float a0 = ss0[lane], a1 = ss0[lane + 32];
        const float ce0 = warp_softmax_ce(a0, a1, lane, lab, nullptr);
        const float n0 = a0 + accS[lane], n1 = a1 + accS[lane + 32];
        const float ce1 = warp_softmax_ce(n0, n1, lane, lab, out + (size_t)LBC + voff);
        if (lane == 0) atomicAdd(&lossAcc, ce0 + ce1);
    }
    __syncthreads();
    if (tid == 0) atomicAdd(&g_buckets[blk & (NBUCKET - 1)], lossAcc);
}

// ---------------------------------------------------------------------------
// Kernel 3: single-warp bucket reduction -> loss scalar. No __syncthreads.
// ---------------------------------------------------------------------------
__global__ void loss_finalize(float* __restrict__ out_loss) {
    const int t = threadIdx.x;     // 32 threads
    float acc = 0.0f;
#pragma unroll
    for (int i = 0; i < NBUCKET / 32; ++i)
        acc += g_buckets[t + i * 32];
#pragma unroll
    for (int o = 16; o; o >>= 1)
        acc += __shfl_xor_sync(0xffffffffu, acc, o);
    if (t == 0) out_loss[0] = acc * (1.0f / (float)LB);
}

// ---------------------------------------------------------------------------
extern "C" void kernel_launch(void* const* d_in, const int* in_sizes, int n_in,
                              void* d_out, int out_size) {
    const float* f    = (const float*)d_in[0];
    const float* s    = (const float*)d_in[1];
    const float* fs   = (const float*)d_in[2];
    const float* ff   = (const float*)d_in[3];
    const float* ss   = (const float*)d_in[4];
    const float* fs_t = (const float*)d_in[5];
    const float* sf_t = (const float*)d_in[6];
    const int* f_lab  = (const int*)d_in[7];
    const int* s_lab  = (const int*)d_in[8];
    float* out = (float*)d_out;

    dim3 g1(L / TL, B, 2);
    msg_kernel<<<g1, 256>>>(f, s);
    main_kernel<<<LB, 256>>>(f, s, fs, ff, ss, fs_t, sf_t, f_lab, s_lab, out);
    loss_finalize<<<1, 32>>>(out + (size_t)2 * LBC);
}

// round 7
// speedup vs baseline: 1.1495x; 1.0335x over previous
#include <cuda_runtime.h>
#include <math.h>

#define L 256
#define B 32
#define C 64
#define LB (L * B)           // 8192
#define LBC (LB * C)         // 524288
#define DMAX 12              // exp(-13^2/8)=6.7e-10: below tolerance here
#define TL 32                // rows per msg block
#define RPT 8                // rows per thread in msg kernel
#define NBUCKET 256

// Scratch (allocation-free rule: __device__ globals)
__device__ float g_fmp[LBC];
__device__ float g_fmf[LBC];
__device__ float g_smp[LBC];
__device__ float g_smf[LBC];
__device__ float g_buckets[NBUCKET];

// Gaussian weights exp(-d*d/8) as COMPILE-TIME literals -> FFMA-imm (rt=1/SMSP)
__device__ __forceinline__ constexpr float wexp(int d) {
    constexpr float w[13] = {
        1.0f,
        0.882496903f,   0.606530660f,   0.324652467f,   0.135335283f,
        0.0439369336f,  0.0111089965f,  0.00218749111f, 0.000335462624f,
        4.00652974e-05f, 3.72665317e-06f, 2.69957964e-07f, 1.52299797e-08f};
    return w[d];
}

// ---------------------------------------------------------------------------
// Kernel 1: Gaussian-decay message passing as a +/-DMAX stencil.
// (R4/R6-proven: ~7.9us) grid: (L/TL, B, 2)  z: 0 -> f, 1 -> s. 256 threads.
// ---------------------------------------------------------------------------
__global__ void __launch_bounds__(256) msg_kernel(const float* __restrict__ f,
                                                  const float* __restrict__ s) {
    __shared__ float tile[(TL + 2 * DMAX) * C];   // 56*64*4 = 14.3 KB

    const int tid = threadIdx.x;
    const int l0  = blockIdx.x * TL;
    const int b   = blockIdx.y;
    const int tz  = blockIdx.z;

    if (blockIdx.x == 0 && blockIdx.y == 0 && blockIdx.z == 0 && tid < NBUCKET)
        g_buckets[tid] = 0.0f;

    const float* __restrict__ x  = (tz == 0) ? f : s;
    float* __restrict__ mp = (tz == 0) ? g_fmp : g_smp;
    float* __restrict__ mf = (tz == 0) ? g_fmf : g_smf;

#pragma unroll
    for (int i = tid; i < (TL + 2 * DMAX) * C; i += 256) {
        int row = i >> 6;
        int c   = i & 63;
        int lg  = l0 - DMAX + row;
        tile[i] = (lg >= 0 && lg < L) ? x[((size_t)lg * B + b) * C + c] : 0.0f;
    }
    __syncthreads();

    const int c  = tid & 63;
    const int j0 = (tid >> 6) * RPT;     // local output row base (0,8,16,24)

    float ap[RPT], af[RPT];
#pragma unroll
    for (int r = 0; r < RPT; ++r) { ap[r] = 0.0f; af[r] = 0.0f; }

#pragma unroll
    for (int k = 0; k < RPT + 2 * DMAX; ++k) {
        const float xi = tile[(j0 + k) * C + c];
#pragma unroll
        for (int r = 0; r < RPT; ++r) {
            const int d = k - DMAX - r;       // compile-time per (k,r)
            if (d >= -DMAX && d <= -1) ap[r] = fmaf(wexp(-d), xi, ap[r]);
            else if (d >= 1 && d <= DMAX) af[r] = fmaf(wexp(d), xi, af[r]);
        }
    }

#pragma unroll
    for (int r = 0; r < RPT; ++r) {
        const int l = l0 + j0 + r;
        const size_t o = ((size_t)l * B + b) * C + c;
        mp[o] = ap[r] / (float)max(l, 1);
        mf[o] = af[r] / (float)max(L - 1 - l, 1);
    }
}

// warp-level softmax + CE over 64 logits (lane holds j=lane and j=lane+32).
__device__ __forceinline__ float warp_softmax_ce(float v0, float v1, int lane,
                                                 int label, float* outp) {
    float m = fmaxf(v0, v1);
#pragma unroll
    for (int o = 16; o; o >>= 1) m = fmaxf(m, __shfl_xor_sync(0xffffffffu, m, o));
    float e0 = __expf(v0 - m), e1 = __expf(v1 - m);
    float sum = e0 + e1;
#pragma unroll
    for (int o = 16; o; o >>= 1) sum += __shfl_xor_sync(0xffffffffu, sum, o);
    if (outp) {
        const float inv = 1.0f / sum;
        outp[lane]      = e0 * inv;
        outp[lane + 32] = e1 * inv;
    }
    const float lse = m + __logf(sum);
    const float vl  = __shfl_sync(0xffffffffu, (label < 32) ? v0 : v1, label & 31);
    return lse - vl;
}

__device__ __forceinline__ float dot4(float4 a, float4 b) {
    return fmaf(a.x, b.x, fmaf(a.y, b.y, fmaf(a.z, b.z, a.w * b.w)));
}

// ---------------------------------------------------------------------------
// Kernel 2: one CTA per (l,b). R6 structure with ONE change: loop order
// swapped to interleave the 5 matrices' loads per rp step (5 independent
// LDG.128 in flight). Reductions remain fully deferred (registers only in
// the hot loop) — the in-loop shuffles are what killed R3.
// ---------------------------------------------------------------------------
__global__ void __launch_bounds__(256, 4)
main_kernel(const float* __restrict__ f,  const float* __restrict__ s,
            const float* __restrict__ fs, const float* __restrict__ ff,
            const float* __restrict__ ss, const float* __restrict__ fs_t,
            const float* __restrict__ sf_t,
            const int* __restrict__ f_lab, const int* __restrict__ s_lab,
            float* __restrict__ out) {
    const int blk = blockIdx.x;                 // l*B + b
    const size_t voff = (size_t)blk * C;
    const size_t moff = (size_t)blk * (C * C);
    const int tid = threadIdx.x;

    __shared__ __align__(16) float sf0[C], ss0[C];
    __shared__ __align__(16) float v_fmp[C], v_fmf[C], v_smp[C], v_smf[C];
    __shared__ __align__(16) float v_fW[C], v_sW[C];
    __shared__ __align__(16) float accF[C], accS[C];
    __shared__ float lossAcc;

    if (tid < C) {
        const float fv = f[voff + tid];
        const float sv = s[voff + tid];
        sf0[tid] = fv;          ss0[tid] = sv;
        v_fW[tid] = 0.5f * fv;  v_sW[tid] = 0.5f * sv;            // W_S
        v_fmp[tid] = 0.5f * g_fmp[voff + tid];                     // W_T folded
        v_fmf[tid] = 0.5f * g_fmf[voff + tid];
        v_smp[tid] = 0.5f * g_smp[voff + tid];
        v_smf[tid] = 0.5f * g_smf[voff + tid];
    }
    if (tid == 0) lossAcc = 0.0f;
    __syncthreads();

    const int w    = tid >> 5;
    const int lane = tid & 31;
    const int half = lane >> 4;   // 0 or 1
    const int li   = lane & 15;   // column group
    const int rbase = (w << 3) + half;

    const float* __restrict__ Mff  = ff   + moff;
    const float* __restrict__ Mss  = ss   + moff;
    const float* __restrict__ Mfs  = fs   + moff;
    const float* __restrict__ Mfst = fs_t + moff;
    const float* __restrict__ Msft = sf_t + moff;

    const float4 vc_fmf = *(const float4*)(v_fmf + (li << 2));
    const float4 vc_smf = *(const float4*)(v_smf + (li << 2));
    const float4 vc_sW  = *(const float4*)(v_sW  + (li << 2));

    float rowF[4], rowS[4];
    float4 colF = make_float4(0.f, 0.f, 0.f, 0.f);
    float4 colS = make_float4(0.f, 0.f, 0.f, 0.f);

    // next_f row: ff@(wT f_mf) + fs@(wS s) + fs_t@(wT s_mf)
    // next_f col: ff^T@(wT f_mp) + sf_t^T@(wT s_mp)
    // next_s row: ss@(wT s_mf) + sf_t@(wT f_mf)
    // next_s col: ss^T@(wT s_mp) + fs^T@(wS f) + fs_t^T@(wT f_mp)
#pragma unroll
    for (int rp = 0; rp < 4; ++rp) {
        const int r   = rbase + (rp << 1);
        const int off = (r << 6) + (li << 2);
        const float4 m0 = *(const float4*)(Mff  + off);
        const float4 m1 = *(const float4*)(Mss  + off);
        const float4 m2 = *(const float4*)(Mfs  + off);
        const float4 m3 = *(const float4*)(Mfst + off);
        const float4 m4 = *(const float4*)(Msft + off);
        const float vr_fmp = v_fmp[r];
        const float vr_smp = v_smp[r];
        const float vr_fW  = v_fW[r];

        rowF[rp] = dot4(m0, vc_fmf) + dot4(m2, vc_sW) + dot4(m3, vc_smf);
        rowS[rp] = dot4(m1, vc_smf) + dot4(m4, vc_fmf);

        colF.x = fmaf(m0.x, vr_fmp, fmaf(m4.x, vr_smp, colF.x));
        colF.y = fmaf(m0.y, vr_fmp, fmaf(m4.y, vr_smp, colF.y));
        colF.z = fmaf(m0.z, vr_fmp, fmaf(m4.z, vr_smp, colF.z));
        colF.w = fmaf(m0.w, vr_fmp, fmaf(m4.w, vr_smp, colF.w));
        colS.x = fmaf(m1.x, vr_smp, fmaf(m2.x, vr_fW, fmaf(m3.x, vr_fmp, colS.x)));
        colS.y = fmaf(m1.y, vr_smp, fmaf(m2.y, vr_fW, fmaf(m3.y, vr_fmp, colS.y)));
        colS.z = fmaf(m1.z, vr_smp, fmaf(m2.z, vr_fW, fmaf(m3.z, vr_fmp, colS.z)));
        colS.w = fmaf(m1.w, vr_smp, fmaf(m2.w, vr_fW, fmaf(m3.w, vr_fmp, colS.w)));
    }

    // ---- deferred row reduction: sum over 16 li-lanes within each half ----
#pragma unroll
    for (int rp = 0; rp < 4; ++rp) {
#pragma unroll
        for (int o = 8; o; o >>= 1) {
            rowF[rp] += __shfl_xor_sync(0xffffffffu, rowF[rp], o);
            rowS[rp] += __shfl_xor_sync(0xffffffffu, rowS[rp], o);
        }
    }
    if (li == 0) {
#pragma unroll
        for (int rp = 0; rp < 4; ++rp) {
            const int r = rbase + (rp << 1);
            accF[r] = rowF[rp];     // exclusive per row -> plain store
            accS[r] = rowS[rp];
        }
    }
    __syncthreads();

    // ---- col reduction: fold odd half into even, then atomics across warps
    colF.x += __shfl_down_sync(0xffffffffu, colF.x, 16);
    colF.y += __shfl_down_sync(0xffffffffu, colF.y, 16);
    colF.z += __shfl_down_sync(0xffffffffu, colF.z, 16);
    colF.w += __shfl_down_sync(0xffffffffu, colF.w, 16);
    colS.x += __shfl_down_sync(0xffffffffu, colS.x, 16);
    colS.y += __shfl_down_sync(0xffffffffu, colS.y, 16);
    colS.z += __shfl_down_sync(0xffffffffu, colS.z, 16);
    colS.w += __shfl_down_sync(0xffffffffu, colS.w, 16);
    if (half == 0) {
        const int cb = li << 2;
        atomicAdd(&accF[cb + 0], colF.x);
        atomicAdd(&accF[cb + 1], colF.y);
        atomicAdd(&accF[cb + 2], colF.z);
        atomicAdd(&accF[cb + 3], colF.w);
        atomicAdd(&accS[cb + 0], colS.x);
        atomicAdd(&accS[cb + 1], colS.y);
        atomicAdd(&accS[cb + 2], colS.z);
        atomicAdd(&accS[cb + 3], colS.w);
    }
    __syncthreads();

    // ---- epilogue: softmax + CE (old & new logits), outputs, loss partial
    if (w == 0) {
        const int lab = f_lab[blk];
        const float a0 = sf0[lane], a1 = sf0[lane + 32];
        const float ce0 = warp_softmax_ce(a0, a1, lane, lab, nullptr);
        const float n0 = a0 + accF[lane], n1 = a1 + accF[lane + 32];
        const float ce1 = warp_softmax_ce(n0, n1, lane, lab, out + voff);
        if (lane == 0) atomicAdd(&lossAcc, ce0 + ce1);
    } else if (w == 1) {
        const int lab = s_lab[blk];
        const float a0 = ss0[lane], a1 = ss0[lane + 32];
        const float ce0 = warp_softmax_ce(a0, a1, lane, lab, nullptr);
        const float n0 = a0 + accS[lane], n1 = a1 + accS[lane + 32];
        const float ce1 = warp_softmax_ce(n0, n1, lane, lab, out + (size_t)LBC + voff);
        if (lane == 0) atomicAdd(&lossAcc, ce0 + ce1);
    }
    __syncthreads();
    if (tid == 0) atomicAdd(&g_buckets[blk & (NBUCKET - 1)], lossAcc);
}

// ---------------------------------------------------------------------------
// Kernel 3: single-warp bucket reduction -> loss scalar. No __syncthreads.
// ---------------------------------------------------------------------------
__global__ void loss_finalize(float* __restrict__ out_loss) {
    const int t = threadIdx.x;     // 32 threads
    float acc = 0.0f;
#pragma unroll
    for (int i = 0; i < NBUCKET / 32; ++i)
        acc += g_buckets[t + i * 32];
#pragma unroll
    for (int o = 16; o; o >>= 1)
        acc += __shfl_xor_sync(0xffffffffu, acc, o);
    if (t == 0) out_loss[0] = acc * (1.0f / (float)LB);
}

// ---------------------------------------------------------------------------
extern "C" void kernel_launch(void* const* d_in, const int* in_sizes, int n_in,
                              void* d_out, int out_size) {
    const float* f    = (const float*)d_in[0];
    const float* s    = (const float*)d_in[1];
    const float* fs   = (const float*)d_in[2];
    const float* ff   = (const float*)d_in[3];
    const float* ss   = (const float*)d_in[4];
    const float* fs_t = (const float*)d_in[5];
    const float* sf_t = (const float*)d_in[6];
    const int* f_lab  = (const int*)d_in[7];
    const int* s_lab  = (const int*)d_in[8];
    float* out = (float*)d_out;

    dim3 g1(L / TL, B, 2);
    msg_kernel<<<g1, 256>>>(f, s);
    main_kernel<<<LB, 256>>>(f, s, fs, ff, ss, fs_t, sf_t, f_lab, s_lab, out);
    loss_finalize<<<1, 32>>>(out + (size_t)2 * LBC);
}